// round 2
// baseline (speedup 1.0000x reference)
#include <cuda_runtime.h>
#include <cstddef>

// Problem constants (fixed shapes): x = (256, 2048, 25, 3, 1) fp32
#define NB_ 256
#define TT 2048
#define NJ 25
#define ROW 75          // 25 joints * 3 channels, floats per frame
#define NI 36           // number of atomic intervals
#define NG 15           // gaussians per segment config
#define MAXF 144        // largest interval length in frames

// Union of gaussian chunk boundaries for nb_fr in {136, 68, 45} over T=2048.
__constant__ int c_bound[NI + 1] = {
    0, 45, 68, 90, 135, 136, 180, 204, 225, 270, 272, 315, 340, 360, 405, 408,
    450, 476, 495, 540, 544, 585, 612, 630, 680, 748, 816, 884, 952, 1088,
    1224, 1360, 1496, 1632, 1768, 1904, 2048};

// Phase-1 scratch: [b][interval][j*9 + e]  (8.3 MB)
__device__ float g_part[(size_t)NB_ * NI * (NJ * 9)];

// ---------------------------------------------------------------------------
// Phase 1: one block per (interval, batch). Coalesced stage of the interval's
// frames into shared, then per-(joint, lane-group) register accumulation of
// the 9 second-moment sums, warp-shuffle reduction over the 8-lane groups,
// coalesced store of the 225 partial sums.
// ---------------------------------------------------------------------------
__global__ __launch_bounds__(256) void k_partial(const float* __restrict__ x) {
    const int i   = blockIdx.x;     // interval
    const int b   = blockIdx.y;     // batch
    const int t0  = c_bound[i];
    const int F   = c_bound[i + 1] - t0;
    const int tid = threadIdx.x;

    __shared__ float sh[MAXF * ROW];     // 43.2 KB
    __shared__ float red[NJ * 9];

    const float* __restrict__ src = x + ((size_t)b * TT + t0) * ROW;
    const int n = F * ROW;
    for (int idx = tid; idx < n; idx += 256)
        sh[idx] = src[idx];
    __syncthreads();

    float a0 = 0.f, a1 = 0.f, a2 = 0.f, a3 = 0.f, a4 = 0.f,
          a5 = 0.f, a6 = 0.f, a7 = 0.f, a8 = 0.f;
    const int j   = tid >> 3;    // joint 0..31 (25 valid)
    const int grp = tid & 7;     // 8-lane frame group
    if (j < NJ) {
        const int base = j * 3;
        for (int f = grp; f < F; f += 8) {
            const float* p = sh + f * ROW + base;
            const float x0 = p[0], x1 = p[1], x2 = p[2];
            a0 += x0 * x0; a1 += x0 * x1; a2 += x0 * x2;
            a3 += x1 * x1; a4 += x1 * x2; a5 += x2 * x2;
            a6 += x0;      a7 += x1;      a8 += x2;
        }
    }
    // Reduce over the 8-lane group (lane&7). All 32 lanes participate.
    #pragma unroll
    for (int d = 4; d >= 1; d >>= 1) {
        a0 += __shfl_down_sync(0xffffffffu, a0, d);
        a1 += __shfl_down_sync(0xffffffffu, a1, d);
        a2 += __shfl_down_sync(0xffffffffu, a2, d);
        a3 += __shfl_down_sync(0xffffffffu, a3, d);
        a4 += __shfl_down_sync(0xffffffffu, a4, d);
        a5 += __shfl_down_sync(0xffffffffu, a5, d);
        a6 += __shfl_down_sync(0xffffffffu, a6, d);
        a7 += __shfl_down_sync(0xffffffffu, a7, d);
        a8 += __shfl_down_sync(0xffffffffu, a8, d);
    }
    if (grp == 0 && j < NJ) {
        float* r = red + j * 9;
        r[0] = a0; r[1] = a1; r[2] = a2; r[3] = a3; r[4] = a4;
        r[5] = a5; r[6] = a6; r[7] = a7; r[8] = a8;
    }
    __syncthreads();
    if (tid < NJ * 9)
        g_part[((size_t)b * NI + i) * (NJ * 9) + tid] = red[tid];
}

// ---------------------------------------------------------------------------
// Phase 2: one block per (joint, batch). Load all 36 interval partials for
// this (b,j), combine into the 45 unique (seg-config, gaussian) moments,
// scale by 1/N, assemble the 4x4 augmented second-moment matrix, and write
// it to all 6 output segments (1->1, 2x replication, 3x replication).
// ---------------------------------------------------------------------------
__global__ __launch_bounds__(64) void k_final(float* __restrict__ out) {
    const int j   = blockIdx.x;   // joint 0..24
    const int b   = blockIdx.y;
    const int tid = threadIdx.x;

    __shared__ float s1[NI * 9];
    __shared__ float fin[45][16];

    const float* __restrict__ base = g_part + (size_t)b * NI * (NJ * 9) + j * 9;
    for (int idx = tid; idx < NI * 9; idx += 64) {
        const int i = idx / 9;
        const int e = idx - i * 9;
        s1[idx] = base[i * (NJ * 9) + e];
    }
    __syncthreads();

    if (tid < 45) {
        const int u  = tid / 15;          // unique seg config
        const int g  = tid - u * 15;      // gaussian
        const int nb = (u == 0) ? 136 : ((u == 1) ? 68 : 45);
        const int lo = g * nb;
        const int hi = (g == 14) ? TT : lo + nb;

        int i0 = 0;
        while (c_bound[i0] != lo) ++i0;

        float s[9];
        #pragma unroll
        for (int e = 0; e < 9; ++e) s[e] = 0.f;
        for (int i = i0; c_bound[i] < hi; ++i) {
            #pragma unroll
            for (int e = 0; e < 9; ++e) s[e] += s1[i * 9 + e];
        }
        const float invN = 1.0f / (float)(hi - lo);
        #pragma unroll
        for (int e = 0; e < 9; ++e) s[e] *= invN;

        float* f = fin[tid];
        f[0]  = s[0]; f[1]  = s[1]; f[2]  = s[2]; f[3]  = s[6];
        f[4]  = s[1]; f[5]  = s[3]; f[6]  = s[4]; f[7]  = s[7];
        f[8]  = s[2]; f[9]  = s[4]; f[10] = s[5]; f[11] = s[8];
        f[12] = s[6]; f[13] = s[7]; f[14] = s[8]; f[15] = 1.0f;
    }
    __syncthreads();

    // out shape: (b, 6, NP=5, NS=15, P=5, 4, 4); j = np*5 + p
    const int np = j / 5;
    const int p  = j - np * 5;
    for (int idx = tid; idx < 6 * NG * 16; idx += 64) {
        const int sg  = idx / (NG * 16);
        const int rem = idx - sg * (NG * 16);
        const int g   = rem >> 4;
        const int e   = rem & 15;
        const int u   = (sg == 0) ? 0 : (sg < 3 ? 1 : 2);
        const size_t o =
            ((((size_t)(b * 6 + sg) * 5 + np) * NG + g) * 5 + p) * 16 + e;
        out[o] = fin[u * 15 + g][e];
    }
}

extern "C" void kernel_launch(void* const* d_in, const int* in_sizes, int n_in,
                              void* d_out, int out_size) {
    const float* x = (const float*)d_in[0];
    float* out = (float*)d_out;
    (void)in_sizes; (void)n_in; (void)out_size;

    k_partial<<<dim3(NI, NB_), 256>>>(x);
    k_final<<<dim3(NJ, NB_), 64>>>(out);
}